// round 6
// baseline (speedup 1.0000x reference)
#include <cuda_runtime.h>
#include <cfloat>

#define TOT 8192
#define BN 16
#define C 64
#define K 20
#define CN 512
#define NW (BN*CN)
#define STEPS 8
#define NBLK 512
#define BN_EPS 1e-5f

// ---- device scratch (static; no allocations) ----
__device__ float  g_xT[(size_t)BN*TOT*C];        // x transposed (b,node,ch) 32MB
__device__ float2 g_ssq[(size_t)BN*TOT];         // per-node (dot(x,w_lo), |x|^2)
__device__ float  g_curves[(size_t)STEPS*NW*C];  // [step][w][ch] 16MB
__device__ float  g_S[2][BN*2*CN];               // double-buffered softmax exchange
__device__ unsigned g_bar;                       // grid barrier counter

__device__ __forceinline__ float dot4(const float4& a, const float4& b) {
    return a.x*b.x + a.y*b.y + a.z*b.z + a.w*b.w;
}
__device__ __forceinline__ float dot8(const float4& a0, const float4& a1,
                                      const float4& b0, const float4& b1) {
    return dot4(a0,b0) + dot4(a1,b1);
}

// ---------------- fused: transpose x -> xT, and per-node (s, |x|^2) ----------------
__global__ __launch_bounds__(256)
void prep_kernel(const float* __restrict__ x, const float* __restrict__ agent_w) {
    __shared__ float tile[64][33];
    int b = blockIdx.y;
    int node0 = blockIdx.x * 32;
    int t = threadIdx.x;
    int ty = t >> 3;      // channel 0..31 (and +32)
    int tx = t & 7;       // float4 index along nodes

    const float* xb = x + (size_t)b * C * TOT;
    float4 v0 = __ldg((const float4*)(xb + (size_t)ty * TOT + node0) + tx);
    float4 v1 = __ldg((const float4*)(xb + (size_t)(ty + 32) * TOT + node0) + tx);
    tile[ty][tx*4+0] = v0.x; tile[ty][tx*4+1] = v0.y;
    tile[ty][tx*4+2] = v0.z; tile[ty][tx*4+3] = v0.w;
    tile[ty+32][tx*4+0] = v1.x; tile[ty+32][tx*4+1] = v1.y;
    tile[ty+32][tx*4+2] = v1.z; tile[ty+32][tx*4+3] = v1.w;
    __syncthreads();

    int node = t >> 3;    // 0..31
    int j = t & 7;        // float4 index along channels
    float4 a = make_float4(tile[4*j+0][node], tile[4*j+1][node],
                           tile[4*j+2][node], tile[4*j+3][node]);
    float4 c = make_float4(tile[32+4*j+0][node], tile[32+4*j+1][node],
                           tile[32+4*j+2][node], tile[32+4*j+3][node]);
    float4* dst = (float4*)(g_xT + ((size_t)b * TOT + node0 + node) * C);
    dst[j] = a; dst[8 + j] = c;

    const float4* wv = (const float4*)agent_w;
    float4 wA = __ldg(&wv[j]), wB = __ldg(&wv[8 + j]);
    float s = dot4(a, wA) + dot4(c, wB);
    float q = dot4(a, a) + dot4(c, c);
    #pragma unroll
    for (int off = 1; off <= 4; off <<= 1) {
        s += __shfl_xor_sync(0xffffffffu, s, off);
        q += __shfl_xor_sync(0xffffffffu, q, off);
    }
    if (j == 0) g_ssq[(size_t)b * TOT + node0 + node] = make_float2(s, q);
}

// ---------------- persistent walk: all 8 steps, 8 lanes/walker ----------------
__global__ __launch_bounds__(128, 4)
void walk_persistent(
    const int* __restrict__ adj, const int* __restrict__ cur0,
    const float* __restrict__ agent_w,
    const float* __restrict__ agent_gamma, const float* __restrict__ agent_beta,
    const float* __restrict__ agent_mean,  const float* __restrict__ agent_var,
    const float* __restrict__ mom_w,
    const float* __restrict__ mom_gamma, const float* __restrict__ mom_beta,
    const float* __restrict__ mom_mean,  const float* __restrict__ mom_var)
{
    int sub = threadIdx.x & 7;
    int w = blockIdx.x * 16 + (threadIdx.x >> 3);
    int b = w >> 9;
    int n = w & 511;

    const float4* wv = (const float4*)agent_w;
    float4 whA = __ldg(&wv[16 + sub]), whB = __ldg(&wv[24 + sub]);  // agent_w[64:128]

    float inv_a  = __ldg(agent_gamma) / sqrtf(__ldg(agent_var) + BN_EPS);
    float mean_a = __ldg(agent_mean);
    float beta_a = __ldg(agent_beta);

    const float* xTb = g_xT + (size_t)b * TOT * C;
    const float2* ssqb = g_ssq + (size_t)b * TOT;

    int cidx = __ldg(&cur0[w]);
    float4 cfA = make_float4(0.f,0.f,0.f,0.f), cfB = cfA;
    float4 pfA = cfA, pfB = cfA;

    for (int step = 0; step < STEPS; step++) {
        float4 cvA, cvB;
        float tpp, n1 = 0.f, cvcf = 0.f, cf2 = 0.f;

        if (step == 0) {
            const float4* pv = (const float4*)(xTb + (size_t)cidx * C);
            pfA = __ldg(&pv[sub]); pfB = __ldg(&pv[8 + sub]);
            tpp = dot8(pfA, pfB, whA, whB);
            #pragma unroll
            for (int off = 1; off <= 4; off <<= 1)
                tpp += __shfl_xor_sync(0xffffffffu, tpp, off);
            cvA = make_float4(0.f,0.f,0.f,0.f); cvB = cvA;
        } else {
            float2 aa = __ldcg(((const float2*)g_S[(step - 1) & 1]) + b * 512 + n);
            float a0 = aa.x, a1 = aa.y;
            pfA.x = cfA.x*a0 + pfA.x*a1;  pfA.y = cfA.y*a0 + pfA.y*a1;
            pfA.z = cfA.z*a0 + pfA.z*a1;  pfA.w = cfA.w*a0 + pfA.w*a1;
            pfB.x = cfB.x*a0 + pfB.x*a1;  pfB.y = cfB.y*a0 + pfB.y*a1;
            pfB.z = cfB.z*a0 + pfB.z*a1;  pfB.w = cfB.w*a0 + pfB.w*a1;
            cvA.x = cfA.x - pfA.x; cvA.y = cfA.y - pfA.y;
            cvA.z = cfA.z - pfA.z; cvA.w = cfA.w - pfA.w;
            cvB.x = cfB.x - pfB.x; cvB.y = cfB.y - pfB.y;
            cvB.z = cfB.z - pfB.z; cvB.w = cfB.w - pfB.w;

            float tppp  = dot8(pfA, pfB, whA, whB);
            float n1pp  = dot8(cvA, cvB, cvA, cvB);
            float cvcfp = dot8(cvA, cvB, cfA, cfB);
            float cf2p  = dot8(cfA, cfB, cfA, cfB);
            #pragma unroll
            for (int off = 1; off <= 4; off <<= 1) {
                tppp  += __shfl_xor_sync(0xffffffffu, tppp, off);
                n1pp  += __shfl_xor_sync(0xffffffffu, n1pp, off);
                cvcfp += __shfl_xor_sync(0xffffffffu, cvcfp, off);
                cf2p  += __shfl_xor_sync(0xffffffffu, cf2p, off);
            }
            tpp = tppp; n1 = sqrtf(n1pp); cvcf = cvcfp; cf2 = cf2p;
        }

        const int* adjp = adj + ((size_t)b * TOT + cidx) * K;
        const int4* adj4 = (const int4*)adjp;

        float best = -FLT_MAX; int ksel = 0;

        if (step == 0) {
            #pragma unroll
            for (int k = 0; k < K; k++) {
                int idx = __ldg(&adjp[k]);
                float2 ssq = __ldg(&ssqb[idx]);
                float lg = (ssq.x + tpp - mean_a) * inv_a + beta_a;
                if (lg > best) { best = lg; ksel = k; }
            }
        } else {
            // batched gathers (full MLP), static register arrays only
            float cvp[K], cfp[K];
            #pragma unroll
            for (int q = 0; q < 5; q++) {
                int4 t4 = __ldg(&adj4[q]);
                int id0 = t4.x, id1 = t4.y, id2 = t4.z, id3 = t4.w;
                const float4* p0 = (const float4*)(xTb + (size_t)id0 * C);
                const float4* p1 = (const float4*)(xTb + (size_t)id1 * C);
                const float4* p2 = (const float4*)(xTb + (size_t)id2 * C);
                const float4* p3 = (const float4*)(xTb + (size_t)id3 * C);
                float4 a0 = __ldg(&p0[sub]), b0 = __ldg(&p0[8+sub]);
                float4 a1 = __ldg(&p1[sub]), b1 = __ldg(&p1[8+sub]);
                float4 a2 = __ldg(&p2[sub]), b2 = __ldg(&p2[8+sub]);
                float4 a3 = __ldg(&p3[sub]), b3 = __ldg(&p3[8+sub]);
                cvp[4*q+0] = dot8(cvA, cvB, a0, b0); cfp[4*q+0] = dot8(cfA, cfB, a0, b0);
                cvp[4*q+1] = dot8(cvA, cvB, a1, b1); cfp[4*q+1] = dot8(cfA, cfB, a1, b1);
                cvp[4*q+2] = dot8(cvA, cvB, a2, b2); cfp[4*q+2] = dot8(cfA, cfB, a2, b2);
                cvp[4*q+3] = dot8(cvA, cvB, a3, b3); cfp[4*q+3] = dot8(cfA, cfB, a3, b3);
            }
            #pragma unroll
            for (int off = 1; off <= 4; off <<= 1) {
                #pragma unroll
                for (int k = 0; k < K; k++) {
                    cvp[k] += __shfl_xor_sync(0xffffffffu, cvp[k], off);
                    cfp[k] += __shfl_xor_sync(0xffffffffu, cfp[k], off);
                }
            }
            // redundant epilogue on all lanes, constant indexing
            #pragma unroll
            for (int k = 0; k < K; k++) {
                int idx = __ldg(&adjp[k]);
                float2 ssq = __ldg(&ssqb[idx]);
                float lg = (ssq.x + tpp - mean_a) * inv_a + beta_a;
                float cc = cvp[k] - cvcf;
                float nn = ssq.y - 2.f * cfp[k] + cf2;
                float cosv = cc / fmaxf(n1 * sqrtf(nn), 1e-8f);
                lg *= fminf(fmaxf(1.f + cosv, 0.f), 1.f);
                if (lg > best) { best = lg; ksel = k; }
            }
        }

        int nidx = __ldg(&adjp[ksel]);
        {
            const float4* pv = (const float4*)(xTb + (size_t)nidx * C);
            cfA = __ldg(&pv[sub]); cfB = __ldg(&pv[8 + sub]);
        }
        cidx = nidx;

        // coalesced curve store: [step][w][ch]
        {
            float4* cvo = (float4*)(g_curves + ((size_t)step * NW + w) * C);
            cvo[sub] = cfA; cvo[8 + sub] = cfB;
        }

        if (step < STEPS - 1) {
            const float4* mv = (const float4*)mom_w;   // 2 rows x 32 float4
            float l0 = dot8(cfA, cfB, __ldg(&mv[sub]),      __ldg(&mv[8 + sub]))
                     + dot8(pfA, pfB, __ldg(&mv[16 + sub]), __ldg(&mv[24 + sub]));
            float l1 = dot8(cfA, cfB, __ldg(&mv[32 + sub]), __ldg(&mv[40 + sub]))
                     + dot8(pfA, pfB, __ldg(&mv[48 + sub]), __ldg(&mv[56 + sub]));
            #pragma unroll
            for (int off = 1; off <= 4; off <<= 1) {
                l0 += __shfl_xor_sync(0xffffffffu, l0, off);
                l1 += __shfl_xor_sync(0xffffffffu, l1, off);
            }
            if (sub == 0) {
                float inv0 = __ldg(&mom_gamma[0]) / sqrtf(__ldg(&mom_var[0]) + BN_EPS);
                float inv1 = __ldg(&mom_gamma[1]) / sqrtf(__ldg(&mom_var[1]) + BN_EPS);
                float m0 = (l0 - __ldg(&mom_mean[0])) * inv0 + __ldg(&mom_beta[0]);
                float m1 = (l1 - __ldg(&mom_mean[1])) * inv1 + __ldg(&mom_beta[1]);
                float mx = fmaxf(m0, m1);
                float e0 = expf(m0 - mx), e1 = expf(m1 - mx);
                float s = e0 + e1;
                g_S[step & 1][b * 1024 + n]       = e0 / s;
                g_S[step & 1][b * 1024 + 512 + n] = e1 / s;
            }
            // ---- grid barrier (all 512 blocks resident by launch_bounds) ----
            __threadfence();
            __syncthreads();
            if (threadIdx.x == 0) {
                atomicAdd(&g_bar, 1u);
                unsigned target = (unsigned)(step + 1) * NBLK;
                while (*((volatile unsigned*)&g_bar) < target) { }
            }
            __syncthreads();
        }
    }
}

// ---------------- reorder: g_curves[step][w][ch] -> out[b][ch][n][step] ----------------
__global__ __launch_bounds__(256)
void reorder_kernel(float* __restrict__ out) {
    __shared__ float tile[16][8 * C + 1];
    int b = blockIdx.x >> 5;
    int n0 = (blockIdx.x & 31) * 16;
    int t = threadIdx.x;

    #pragma unroll
    for (int step = 0; step < STEPS; step++) {
        #pragma unroll
        for (int i4 = 0; i4 < 4; i4++) {
            int i = i4 * 4 + (t >> 6);
            int ch = t & 63;
            int w = b * CN + n0 + i;
            tile[i][step * 64 + ch] =
                g_curves[((size_t)step * NW + w) * C + ch];
        }
    }
    __syncthreads();

    int i = t & 15, ch0 = t >> 4;
    #pragma unroll
    for (int cc = 0; cc < 4; cc++) {
        int ch = ch0 + cc * 16;
        float v[8];
        #pragma unroll
        for (int s = 0; s < STEPS; s++) v[s] = tile[i][s * 64 + ch];
        float4* dst = (float4*)(out +
            ((((size_t)b * C + ch) * CN) + n0 + i) * STEPS);
        dst[0] = make_float4(v[0], v[1], v[2], v[3]);
        dst[1] = make_float4(v[4], v[5], v[6], v[7]);
    }
}

extern "C" void kernel_launch(void* const* d_in, const int* in_sizes, int n_in,
                              void* d_out, int out_size) {
    const float* x          = (const float*)d_in[1];
    const int*   adj        = (const int*)  d_in[2];
    const int*   cur        = (const int*)  d_in[3];
    const float* agent_w    = (const float*)d_in[4];
    const float* agent_gamma= (const float*)d_in[5];
    const float* agent_beta = (const float*)d_in[6];
    const float* agent_mean = (const float*)d_in[7];
    const float* agent_var  = (const float*)d_in[8];
    const float* mom_w      = (const float*)d_in[9];
    const float* mom_gamma  = (const float*)d_in[10];
    const float* mom_beta   = (const float*)d_in[11];
    const float* mom_mean   = (const float*)d_in[12];
    const float* mom_var    = (const float*)d_in[13];
    float* out = (float*)d_out;

    // reset grid-barrier counter (memset node is graph-capturable)
    void* bar_addr = nullptr;
    cudaGetSymbolAddress(&bar_addr, g_bar);
    cudaMemsetAsync(bar_addr, 0, sizeof(unsigned));

    dim3 pg(TOT / 32, BN);
    prep_kernel<<<pg, 256>>>(x, agent_w);

    walk_persistent<<<NBLK, 128>>>(adj, cur, agent_w, agent_gamma, agent_beta,
        agent_mean, agent_var, mom_w, mom_gamma, mom_beta, mom_mean, mom_var);

    reorder_kernel<<<BN * (CN / 16), 256>>>(out);
}